// round 11
// baseline (speedup 1.0000x reference)
#include <cuda_runtime.h>
#include <cstdint>

// Problem constants
#define NB      32
#define CDIM    256
#define HWN     4096
#define KCODES  1024
#define N_VEC   (NB * HWN)        // 131072
#define N_ZQ    (NB * CDIM * HWN) // 33554432

#define MARGIN  2.0e-3f
#define CINF    3.4e38f
#define NKQ     64                // k-quads (256/4)

// ---------------- static device scratch ----------------
__device__ uint32_t g_e8[NKQ * KCODES];  // packed int8 codebook [kq][n]
__device__ float    g_se[KCODES];        // ||e||^2 (exact fp32)
__device__ float    g_sc[KCODES];        // per-code dequant: codemax/127
__device__ double   g_loss;

__device__ __forceinline__ uint32_t smem_u32(const void* p) {
    uint32_t a;
    asm("{ .reg .u64 t; cvta.to.shared.u64 t, %1; cvt.u32.u64 %0, t; }"
        : "=r"(a) : "l"(p));
    return a;
}
#define CP_ASYNC16(dst, src) \
    asm volatile("cp.async.cg.shared.global [%0], [%1], 16;" :: "r"(dst), "l"(src))
#define CP_COMMIT() asm volatile("cp.async.commit_group;" ::: "memory")
#define CP_WAIT(n)  asm volatile("cp.async.wait_group %0;" :: "n"(n) : "memory")

// ---------------------------------------------------------------------------
// Codebook prep: exact ||e||^2, per-code maxabs, int8 pack into [kq][n].
// ---------------------------------------------------------------------------
__global__ void cb_prep_kernel(const float* __restrict__ cb) {
    int n = blockIdx.x, t = threadIdx.x;
    float v = cb[n * CDIM + t];
    __shared__ float red[256];
    __shared__ float sh_e[256];
    __shared__ float qs_sh;
    sh_e[t] = v;
    red[t] = __fmul_rn(v, v);
    __syncthreads();
    for (int s = 128; s > 0; s >>= 1) {
        if (t < s) red[t] = __fadd_rn(red[t], red[t + s]);
        __syncthreads();
    }
    if (t == 0) {
        g_se[n] = red[0];
        if (n == 0) g_loss = 0.0;
    }
    __syncthreads();
    red[t] = fabsf(v);
    __syncthreads();
    for (int s = 128; s > 0; s >>= 1) {
        if (t < s) red[t] = fmaxf(red[t], red[t + s]);
        __syncthreads();
    }
    if (t == 0) {
        float mx = red[0];
        g_sc[n] = mx * (1.0f / 127.0f);
        qs_sh = (mx > 0.0f) ? (127.0f / mx) : 0.0f;
    }
    __syncthreads();
    float qs = qs_sh;
    if (t < 64) {
        int q[4];
#pragma unroll
        for (int j = 0; j < 4; j++) {
            float x = sh_e[t * 4 + j] * qs;
            x = fminf(fmaxf(x, -127.0f), 127.0f);
            q[j] = __float2int_rn(x);
        }
        g_e8[t * KCODES + n] = (uint32_t)((q[0] & 255) | ((q[1] & 255) << 8) |
                                          ((q[2] & 255) << 16) | ((q[3] & 255) << 24));
    }
}

// ---------------------------------------------------------------------------
// Fused main: int8 dp4a prefilter GEMM + margin filter + exact in-CTA
// rescore + sz + gather/loss/indices. 512 threads, 128 vecs x 1024 codes.
// ---------------------------------------------------------------------------
#define SM_ZS  0         // 131072 : z fp32 [256k][128m]
#define SM_Z8  131072    // 32768  : z int8 packed [64kq][128m] u32
#define SM_B   163840    // 2x8192 : B chunk [16kq][128n] u32
#define SM_SE  180224    // 4096
#define SM_SC  184320    // 4096
#define SM_SZ  188416    // 512
#define SM_DQ  188928    // 512 : rowmax/127
#define SM_QS  189440    // 512 : 127/rowmax
#define SM_IDX 189952    // 512
#define SM_CNT 190464    // 32
#define SM_TOT 190496
// resolution overlay inside [SM_Z8, SM_B+16384):
#define OV_RM    131072  // 128 x 33 f32 (padded, conflict-free)
#define OV_GMIN  147968  // 512
#define OV_PAIR  148480  // 2048 u32
#define OV_KEY   156672  // 128 u64
#define OV_CNTM  157696  // 128 int
#define OV_OVF   158208  // 128 int
#define OV_LASTN 158720  // 128 int
#define OV_OVFL  159232  // 128 int

__global__ void __launch_bounds__(512, 1)
vq_main_kernel(const float* __restrict__ z, const float* __restrict__ cb,
               float* __restrict__ out, int mode) {
    extern __shared__ __align__(1024) float smf[];
    char* sm = (char*)smf;
    const uint32_t sb = smem_u32(sm);
    const int tid = threadIdx.x;
    const int w = tid >> 5, lane = tid & 31;
    const int g = w >> 3, w8 = w & 7;
    const int s = lane >> 3, mc = lane & 7;
    const int m0 = blockIdx.x * 128;
    const int b   = m0 >> 12;
    const int hw0 = m0 & (HWN - 1);

    float* zS  = smf;
    float* seS = (float*)(sm + SM_SE);
    float* scS = (float*)(sm + SM_SC);
    float* szS = (float*)(sm + SM_SZ);
    float* dqS = (float*)(sm + SM_DQ);
    float* qsS = (float*)(sm + SM_QS);
    int*   idxS = (int*)(sm + SM_IDX);
    uint32_t* z8S = (uint32_t*)(sm + SM_Z8);

    for (int i = tid; i < KCODES; i += 512) { seS[i] = g_se[i]; scS[i] = g_sc[i]; }

    // z tile: [256 k][128 m] fp32, coalesced
    for (int it = 0; it < 16; it++) {
        int idx = tid + it * 512;
        int c = idx >> 5, mq = idx & 31;
        float4 v = *(const float4*)(z + (((size_t)(b * CDIM + c)) << 12) + hw0 + (mq << 2));
        *(float4*)(zS + c * 128 + (mq << 2)) = v;
    }
    // prefetch B chunk 0 (tile 0): [16kq][128n]
    {
        int row = tid >> 5, col = tid & 31;
        CP_ASYNC16(sb + SM_B + row * 512 + col * 16, g_e8 + row * KCODES + col * 4);
        CP_COMMIT();
    }
    __syncthreads();

    // sz (reference order: serial ascending c, unfused) + rowmax
    if (tid < 128) {
        float a = 0.0f, am = 0.0f;
        for (int c = 0; c < CDIM; c++) {
            float x = zS[c * 128 + tid];
            a = __fadd_rn(a, __fmul_rn(x, x));
            am = fmaxf(am, fabsf(x));
        }
        szS[tid] = a;
        dqS[tid] = am * (1.0f / 127.0f);
        qsS[tid] = (am > 0.0f) ? (127.0f / am) : 0.0f;
    }
    __syncthreads();

    // quantize z -> z8S [kq][m]
    for (int it = 0; it < 16; it++) {
        int idx = tid + it * 512;
        int kq = idx >> 7, m = idx & 127;
        float qs = qsS[m];
        int q[4];
#pragma unroll
        for (int j = 0; j < 4; j++) {
            float x = zS[(kq * 4 + j) * 128 + m] * qs;
            x = fminf(fmaxf(x, -127.0f), 127.0f);
            q[j] = __float2int_rn(x);
        }
        z8S[kq * 128 + m] = (uint32_t)((q[0] & 255) | ((q[1] & 255) << 8) |
                                       ((q[2] & 255) << 16) | ((q[3] & 255) << 24));
    }

    // per-thread margin-scan state: 8 m rows, 2 candidate slots each
    float rm[8], c0d[8], c1d[8];
    int c0i[8], c1i[8];
    unsigned ovfm = 0;
#pragma unroll
    for (int i = 0; i < 8; i++) { rm[i] = CINF; c0d[i] = CINF; c1d[i] = CINF; c0i[i] = 0; c1i[i] = 0; }

    int acc[32];
#pragma unroll
    for (int i = 0; i < 32; i++) acc[i] = 0;

    __syncthreads();

    // GEMM: 32 chunks = 8 tiles(128n) x 4 kq-chunks(16kq)
    for (int cidx = 0; cidx < 32; cidx++) {
        if (cidx + 1 < 32) {
            int t2 = (cidx + 1) >> 2, ch2 = (cidx + 1) & 3;
            int row = tid >> 5, col = tid & 31;
            CP_ASYNC16(sb + SM_B + ((cidx + 1) & 1) * 8192 + row * 512 + col * 16,
                       g_e8 + (size_t)(ch2 * 16 + row) * KCODES + t2 * 128 + col * 4);
            CP_COMMIT();
            CP_WAIT(1);
        } else {
            CP_WAIT(0);
        }
        __syncthreads();

        const uint32_t* bT = (const uint32_t*)(sm + SM_B + (cidx & 1) * 8192);
        const int ch = cidx & 3;
#pragma unroll
        for (int kqc = 0; kqc < 16; kqc++) {
            const uint32_t* Ap = z8S + (ch * 16 + kqc) * 128 + g * 64 + mc * 4;
            uint4 a0 = *(const uint4*)Ap;
            uint4 a1 = *(const uint4*)(Ap + 32);
            const uint32_t* Bp = bT + kqc * 128 + w8 * 16 + s * 4;
            uint4 b0 = *(const uint4*)Bp;
            uint32_t av[8] = {a0.x, a0.y, a0.z, a0.w, a1.x, a1.y, a1.z, a1.w};
            uint32_t bv[4] = {b0.x, b0.y, b0.z, b0.w};
#pragma unroll
            for (int mi = 0; mi < 8; mi++)
#pragma unroll
                for (int ni = 0; ni < 4; ni++)
                    acc[mi * 4 + ni] = __dp4a((int)av[mi], (int)bv[ni], acc[mi * 4 + ni]);
        }
        __syncthreads();

        if ((cidx & 3) == 3) {
            // epilogue for tile cidx>>2: approx dist + margin-candidate update
            const int t2 = cidx >> 2;
#pragma unroll
            for (int ni = 0; ni < 4; ni++) {
                const int n = t2 * 128 + w8 * 16 + s * 4 + ni;
                const float se = seS[n], sc = scS[n];
#pragma unroll
                for (int mi = 0; mi < 8; mi++) {
                    const int m = g * 64 + mc * 4 + (mi & 3) + ((mi >> 2) << 5);
                    float dot = (float)acc[mi * 4 + ni] * dqS[m] * sc;
                    float d = szS[m] + se - 2.0f * dot;
                    if (d < rm[mi] + MARGIN) {
                        if (d < rm[mi]) rm[mi] = d;
                        if (!(ovfm & (1u << mi))) {
                            if (c0d[mi] >= rm[mi] + MARGIN) {
                                c0d[mi] = c1d[mi]; c0i[mi] = c1i[mi]; c1d[mi] = CINF;
                            }
                            if (c1d[mi] >= rm[mi] + MARGIN) c1d[mi] = CINF;
                            if (c0d[mi] == CINF)      { c0d[mi] = d; c0i[mi] = n; }
                            else if (c1d[mi] == CINF) { c1d[mi] = d; c1i[mi] = n; }
                            else ovfm |= (1u << mi);
                        }
                    }
                }
            }
#pragma unroll
            for (int i = 0; i < 32; i++) acc[i] = 0;
        }
    }

    // ---- resolution ----
    float* RMS   = (float*)(sm + OV_RM);
    float* gminS = (float*)(sm + OV_GMIN);
    uint32_t* pairs = (uint32_t*)(sm + OV_PAIR);
    unsigned long long* keyS = (unsigned long long*)(sm + OV_KEY);
    int* cntmS = (int*)(sm + OV_CNTM);
    int* ovfS  = (int*)(sm + OV_OVF);
    int* lastnS = (int*)(sm + OV_LASTN);
    int* ovflS  = (int*)(sm + OV_OVFL);
    int* cnt2   = (int*)(sm + SM_CNT);

    if (tid < 128) { cntmS[tid] = 0; ovfS[tid] = 0; keyS[tid] = ~0ull; lastnS[tid] = 0; }
    if (tid == 0) { cnt2[0] = 0; cnt2[1] = 0; }
    __syncthreads();

    const int pidx = w8 * 4 + s;
#pragma unroll
    for (int mi = 0; mi < 8; mi++) {
        const int m = g * 64 + mc * 4 + (mi & 3) + ((mi >> 2) << 5);
        RMS[m * 33 + pidx] = rm[mi];
        if (ovfm & (1u << mi)) atomicOr(&ovfS[m], 1);
    }
    __syncthreads();

    if (tid < 128) {
        float gm = CINF;
#pragma unroll 8
        for (int p = 0; p < 32; p++) gm = fminf(gm, RMS[tid * 33 + p]);
        gminS[tid] = gm;
    }
    __syncthreads();

#pragma unroll
    for (int mi = 0; mi < 8; mi++) {
        const int m = g * 64 + mc * 4 + (mi & 3) + ((mi >> 2) << 5);
        if (ovfS[m]) continue;
        float gm = gminS[m];
        if (c0d[mi] != CINF && c0d[mi] < gm + MARGIN) {
            int p = atomicAdd(&cnt2[0], 1);
            if (p < 2048) { pairs[p] = (uint32_t)((m << 10) | c0i[mi]); atomicAdd(&cntmS[m], 1); lastnS[m] = c0i[mi]; }
            else atomicExch(&ovfS[m], 1);
        }
        if (c1d[mi] != CINF && c1d[mi] < gm + MARGIN) {
            int p = atomicAdd(&cnt2[0], 1);
            if (p < 2048) { pairs[p] = (uint32_t)((m << 10) | c1i[mi]); atomicAdd(&cntmS[m], 1); lastnS[m] = c1i[mi]; }
            else atomicExch(&ovfS[m], 1);
        }
    }
    __syncthreads();

    if (tid < 128) {
        if (ovfS[tid] || cntmS[tid] == 0) {
            int o = atomicAdd(&cnt2[1], 1);
            ovflS[o] = tid;
        } else if (cntmS[tid] == 1) {
            idxS[tid] = lastnS[tid];
        }
    }
    __syncthreads();

    // exact pair rescore (bitwise reference recipe)
    const int np = min(cnt2[0], 2048);
    for (int p = tid; p < np; p += 512) {
        uint32_t e = pairs[p];
        int m = e >> 10, n = e & 1023;
        if (ovfS[m] || cntmS[m] == 1) continue;
        const float* er = cb + (size_t)n * CDIM;
        float a2 = 0.0f;
#pragma unroll 16
        for (int k = 0; k < CDIM; k++) a2 = __fmaf_rn(zS[k * 128 + m], __ldg(er + k), a2);
        float d = __fsub_rn(__fadd_rn(szS[m], seS[n]), __fmul_rn(2.0f, a2));
        unsigned long long kk = ((unsigned long long)__float_as_uint(d) << 32) | (unsigned)n;
        atomicMin(&keyS[m], kk);
    }

    // exact full rescan for overflow rows (warp per row)
    const int novf = cnt2[1];
    for (int o = w; o < novf; o += 16) {
        int row = ovflS[o];
        float sz = szS[row];
        float bd = __int_as_float(0x7f800000);
        int bi = 0x7fffffff;
        for (int c = lane; c < KCODES; c += 32) {
            const float* er = cb + (size_t)c * CDIM;
            float a2 = 0.0f;
#pragma unroll 16
            for (int k = 0; k < CDIM; k++) a2 = __fmaf_rn(zS[k * 128 + row], __ldg(er + k), a2);
            float d = __fsub_rn(__fadd_rn(sz, seS[c]), __fmul_rn(2.0f, a2));
            if (d < bd) { bd = d; bi = c; }
        }
#pragma unroll
        for (int off = 16; off > 0; off >>= 1) {
            float od = __shfl_xor_sync(0xffffffffu, bd, off);
            int   oi = __shfl_xor_sync(0xffffffffu, bi, off);
            if (od < bd || (od == bd && oi < bi)) { bd = od; bi = oi; }
        }
        if (lane == 0) idxS[row] = bi;
    }
    __syncthreads();

    if (tid < 128 && !ovfS[tid] && cntmS[tid] >= 2)
        idxS[tid] = (int)(keyS[tid] & 0xffffffffu);
    __syncthreads();

    if (mode >= 2 && tid < 128)
        out[N_ZQ + 2 + m0 + tid] = (float)idxS[tid];

    // ---- fused gather: z from smem, e from L2, coalesced stores ----
    {
        const int gm = tid & 127, gh = tid >> 7;   // row, column-quarter
        const int idx = idxS[gm];
        const float4* er4 = (const float4*)(cb + (size_t)idx * CDIM) + gh * 16;
        float lsum = 0.0f;
#pragma unroll 4
        for (int cq = 0; cq < 16; cq++) {
            float4 e4 = er4[cq];
            int c0 = gh * 64 + cq * 4;
            float ev[4] = {e4.x, e4.y, e4.z, e4.w};
#pragma unroll
            for (int j = 0; j < 4; j++) {
                int c = c0 + j;
                float zv = zS[c * 128 + gm];
                float t  = __fsub_rn(ev[j], zv);           // e - z
                out[(((size_t)(b * CDIM + c)) << 12) + hw0 + gm] = __fadd_rn(zv, t);
                lsum = __fmaf_rn(t, t, lsum);
            }
        }
        for (int o = 16; o > 0; o >>= 1)
            lsum += __shfl_down_sync(0xffffffffu, lsum, o);
        if (lane == 0) atomicAdd(&g_loss, (double)lsum);
    }
}

__global__ void finalize_kernel(float* __restrict__ out, int mode) {
    if (mode >= 1) {
        float mean = (float)(g_loss / (double)N_ZQ);
        out[N_ZQ]     = mean;          // codebook_loss
        out[N_ZQ + 1] = 0.25f * mean;  // commitment_loss = exactly 0.25 * mean
    }
}

// ---------------------------------------------------------------------------
extern "C" void kernel_launch(void* const* d_in, const int* in_sizes, int n_in,
                              void* d_out, int out_size) {
    const float* z  = (const float*)d_in[0];
    const float* cb = (const float*)d_in[1];
    float* out = (float*)d_out;

    int mode = 0;
    if (out_size >= N_ZQ + 2) mode = 1;
    if (out_size >= N_ZQ + 2 + N_VEC) mode = 2;

    cudaFuncSetAttribute(vq_main_kernel,
                         cudaFuncAttributeMaxDynamicSharedMemorySize, SM_TOT);

    cb_prep_kernel<<<KCODES, 256>>>(cb);
    vq_main_kernel<<<N_VEC / 128, 512, SM_TOT>>>(z, cb, out, mode);
    finalize_kernel<<<1, 1>>>(out, mode);
}